// round 6
// baseline (speedup 1.0000x reference)
#include <cuda_runtime.h>
#include <math.h>

// ACT_R activation recurrence — wavefront column sweep, 2 batches per block.
// sp: [S=512, B=256, 1] f32 (sorted along S).  w: [a, c, s, tau, h].
// out: [S-1, B, 1] f32.
//
//   E_i = sum_{j<i} max(sc_i - sc_j, 1)^{p_j},  p_j = -(c*E_j + a),  E_0 = 0
//   out[i-1] = sigmoid((log(E_i) - tau)/s)
//
// One block handles 2 batch elements (grid = 128 -> 1 block/SM, balanced).
// 512 threads; thread owns one row per batch. p_j for both batches published
// as one volatile 64-bit smem word (NaN sentinel). Row blocks are permuted
// across warps so each SMSP gets an equal share of the triangular workload.

#define S_LEN 512
#define BATCH 256
#define NB 2

__device__ __forceinline__ float ex2f(float x) {
    float y; asm("ex2.approx.ftz.f32 %0, %1;" : "=f"(y) : "f"(x)); return y;
}
__device__ __forceinline__ float lg2f(float x) {
    float y; asm("lg2.approx.ftz.f32 %0, %1;" : "=f"(y) : "f"(x)); return y;
}
__device__ __forceinline__ float2 lds_v2_vol(const float2* p) {
    float2 v; unsigned a = (unsigned)__cvta_generic_to_shared(p);
    asm volatile("ld.volatile.shared.v2.f32 {%0,%1}, [%2];"
                 : "=f"(v.x), "=f"(v.y) : "r"(a));
    return v;
}
__device__ __forceinline__ void sts_v2_vol(float2* p, float x, float y) {
    unsigned a = (unsigned)__cvta_generic_to_shared(p);
    asm volatile("st.volatile.shared.v2.f32 [%0], {%1,%2};"
                 :: "r"(a), "f"(x), "f"(y));
}

__global__ void __launch_bounds__(S_LEN, 1)
actr_kernel(const float* __restrict__ sp, const float* __restrict__ w,
            float* __restrict__ out) {
    __shared__ float  sc0[S_LEN];
    __shared__ float  sc1[S_LEN];
    __shared__ float2 psm[S_LEN];   // {p_batch0, p_batch1}, NaN = not published

    const int b0   = blockIdx.x * NB;
    const int tid  = threadIdx.x;
    const int wid  = tid >> 5;
    const int lane = tid & 31;

    // SMSP load balancing: row-block workload ~ blk; permute so each SMSP
    // (wid&3) gets blocks summing to 30: {0,15,7,8},{1,14,6,9},{2,13,5,10},{3,12,4,11}
    const int q   = wid >> 2;
    const int blk = (q == 0) ? wid
                  : (q == 1) ? (19 - wid)
                  : (q == 2) ? (15 - wid)
                  : (wid - 4);
    const int base = blk * 32;
    const int t    = base + lane;

    const float a = w[0], c = w[1], s = w[2], tau = w[3], h = w[4];
    const float scale = 86400.0f * h;

    const float my0 = sp[t * BATCH + b0    ] * scale;
    const float my1 = sp[t * BATCH + b0 + 1] * scale;
    sc0[t] = my0;
    sc1[t] = my1;
    const float qnan = __int_as_float(0x7fc00000);
    psm[t] = make_float2(qnan, qnan);
    __syncthreads();

    float accA0 = 0.f, accB0 = 0.f;   // dual accumulators per batch for FADD ILP
    float accA1 = 0.f, accB1 = 0.f;

    // ---- far off-diagonal columns (group-of-4 poll; publish is in order) ----
    int lim = base - 32; if (lim < 0) lim = 0;
    for (int j = 0; j < lim; j += 4) {
        float2 p3 = lds_v2_vol(&psm[j + 3]);
        while (p3.x != p3.x) { __nanosleep(32); p3 = lds_v2_vol(&psm[j + 3]); }
        asm volatile("" ::: "memory");
        float2 p0 = lds_v2_vol(&psm[j + 0]);
        float2 p1 = lds_v2_vol(&psm[j + 1]);
        float2 p2 = lds_v2_vol(&psm[j + 2]);
        float l00 = lg2f(fmaxf(my0 - sc0[j + 0], 1.f));
        float l01 = lg2f(fmaxf(my0 - sc0[j + 1], 1.f));
        float l02 = lg2f(fmaxf(my0 - sc0[j + 2], 1.f));
        float l03 = lg2f(fmaxf(my0 - sc0[j + 3], 1.f));
        float l10 = lg2f(fmaxf(my1 - sc1[j + 0], 1.f));
        float l11 = lg2f(fmaxf(my1 - sc1[j + 1], 1.f));
        float l12 = lg2f(fmaxf(my1 - sc1[j + 2], 1.f));
        float l13 = lg2f(fmaxf(my1 - sc1[j + 3], 1.f));
        accA0 += ex2f(p0.x * l00);  accB0 += ex2f(p1.x * l01);
        accA0 += ex2f(p2.x * l02);  accB0 += ex2f(p3.x * l03);
        accA1 += ex2f(p0.y * l10);  accB1 += ex2f(p1.y * l11);
        accA1 += ex2f(p2.y * l12);  accB1 += ex2f(p3.y * l13);
    }

    // ---- immediate predecessor block: eager per-column (track the wavefront) ----
    for (int j = lim; j < base; ++j) {
        float2 p = lds_v2_vol(&psm[j]);
        while (p.x != p.x) { p = lds_v2_vol(&psm[j]); }
        float l0 = lg2f(fmaxf(my0 - sc0[j], 1.f));
        float l1 = lg2f(fmaxf(my1 - sc1[j], 1.f));
        if (j & 1) { accB0 += ex2f(p.x * l0);  accB1 += ex2f(p.y * l1); }
        else       { accA0 += ex2f(p.x * l0);  accA1 += ex2f(p.y * l1); }
    }
    float acc0 = accA0 + accB0;
    float acc1 = accA1 + accB1;

    // ---- diagonal block: serial chain via shfl, publish for successor warps ----
    float pm0 = 0.f, pm1 = 0.f;
    #pragma unroll
    for (int k = 0; k < 32; ++k) {
        // ld's depend only on timestamps: off the chain, issue before the shfl
        float l0 = lg2f(fmaxf(my0 - sc0[base + k], 1.f));
        float l1 = lg2f(fmaxf(my1 - sc1[base + k], 1.f));
        if (lane == k) {
            pm0 = -fmaf(c, acc0, a);
            pm1 = -fmaf(c, acc1, a);
            sts_v2_vol(&psm[base + k], pm0, pm1);   // publish ASAP
        }
        float pj0 = __shfl_sync(0xffffffffu, pm0, k);
        float pj1 = __shfl_sync(0xffffffffu, pm1, k);
        if (lane > k) {
            acc0 += ex2f(pj0 * l0);
            acc1 += ex2f(pj1 * l1);
        }
    }

    // ---- epilogue: sigmoid((m - tau)/s), m = log(E) ----
    if (t >= 1) {
        const float LN2 = 0.69314718055994530942f;
        const float inv_sln2 = 1.0f / (s * LN2);
        float m0 = lg2f(acc0) * LN2;
        float m1 = lg2f(acc1) * LN2;
        float e0 = ex2f((tau - m0) * inv_sln2);
        float e1 = ex2f((tau - m1) * inv_sln2);
        out[(t - 1) * BATCH + b0    ] = __fdividef(1.f, 1.f + e0);
        out[(t - 1) * BATCH + b0 + 1] = __fdividef(1.f, 1.f + e1);
    }
}

extern "C" void kernel_launch(void* const* d_in, const int* in_sizes, int n_in,
                              void* d_out, int out_size) {
    const float* sp = (const float*)d_in[0];
    const float* w  = (const float*)d_in[1];
    float* out      = (float*)d_out;
    (void)in_sizes; (void)n_in; (void)out_size;
    actr_kernel<<<BATCH / NB, S_LEN>>>(sp, w, out);
}

// round 7
// speedup vs baseline: 1.5149x; 1.5149x over previous
#include <cuda_runtime.h>
#include <math.h>

// ACT_R activation recurrence — wavefront column sweep.
// sp: [S=512, B=256, 1] f32 (sorted along S).  w: [a, c, s, tau, h].
// out: [S-1, B, 1] f32.
//
//   E_i = sum_{j<i} max(sc_i - sc_j, 1)^{p_j},  p_j = -(c*E_j + a),  E_0 = 0
//   out[i-1] = sigmoid((log(E_i) - tau)/s)
//
// One block per batch element (grid=256), one thread per row (block=512).
// p_j published via NaN-sentinel float in smem. Warp's own 32-row diagonal
// runs in-warp via shfl. lg2(d) never depends on p -> issued BEFORE the poll
// so only ex2 sits on the wavefront. Immediate-predecessor columns are
// consumed eagerly (per-column hot spin) to track the wavefront; far columns
// use group-of-8 polling with nanosleep backoff. Row blocks permuted across
// warps so each SMSP gets an equal share of the triangular workload.

#define S_LEN 512
#define BATCH 256

__device__ __forceinline__ float ex2f(float x) {
    float y; asm("ex2.approx.ftz.f32 %0, %1;" : "=f"(y) : "f"(x)); return y;
}
__device__ __forceinline__ float lg2f(float x) {
    float y; asm("lg2.approx.ftz.f32 %0, %1;" : "=f"(y) : "f"(x)); return y;
}

__global__ void __launch_bounds__(S_LEN, 2)
actr_kernel(const float* __restrict__ sp, const float* __restrict__ w,
            float* __restrict__ out) {
    __shared__ float sc[S_LEN];     // scaled timestamps for this batch element
    __shared__ float psm[S_LEN];    // published exponents p_j (NaN = not ready)

    const int b    = blockIdx.x;
    const int tid  = threadIdx.x;
    const int wid  = tid >> 5;
    const int lane = tid & 31;

    // SMSP load balancing: row-block workload ~ blk; permute so each SMSP
    // (wid&3) gets blocks summing to 30: {0,15,7,8},{1,14,6,9},{2,13,5,10},{3,12,4,11}
    const int q   = wid >> 2;
    const int blk = (q == 0) ? wid
                  : (q == 1) ? (19 - wid)
                  : (q == 2) ? (15 - wid)
                  : (wid - 4);
    const int base = blk * 32;
    const int t    = base + lane;           // owned row

    const float a = w[0], c = w[1], s = w[2], tau = w[3], h = w[4];
    const float scale = 86400.0f * h;

    const float my_sc = sp[t * BATCH + b] * scale;
    sc[t]  = my_sc;
    psm[t] = __int_as_float(0x7fc00000);    // NaN sentinel
    __syncthreads();

    volatile float* vp = psm;
    float accA = 0.f, accB = 0.f;           // dual accumulators for FADD ILP

    // ---- far off-diagonal columns: groups of 8, lg2 issued BEFORE the poll ----
    int lim = base - 32; if (lim < 0) lim = 0;   // base,lim are multiples of 32
    for (int j = 0; j < lim; j += 8) {
        float l0 = lg2f(fmaxf(my_sc - sc[j + 0], 1.f));
        float l1 = lg2f(fmaxf(my_sc - sc[j + 1], 1.f));
        float l2 = lg2f(fmaxf(my_sc - sc[j + 2], 1.f));
        float l3 = lg2f(fmaxf(my_sc - sc[j + 3], 1.f));
        float l4 = lg2f(fmaxf(my_sc - sc[j + 4], 1.f));
        float l5 = lg2f(fmaxf(my_sc - sc[j + 5], 1.f));
        float l6 = lg2f(fmaxf(my_sc - sc[j + 6], 1.f));
        float l7 = lg2f(fmaxf(my_sc - sc[j + 7], 1.f));
        // publishes are strictly in column order: once j+7 is ready, all are
        float p7 = vp[j + 7];
        while (__isnanf(p7)) { __nanosleep(32); p7 = vp[j + 7]; }
        asm volatile("" ::: "memory");      // keep p reads below the poll
        float p0 = vp[j + 0];
        float p1 = vp[j + 1];
        float p2 = vp[j + 2];
        float p3 = vp[j + 3];
        float p4 = vp[j + 4];
        float p5 = vp[j + 5];
        float p6 = vp[j + 6];
        accA += ex2f(p0 * l0);  accB += ex2f(p1 * l1);
        accA += ex2f(p2 * l2);  accB += ex2f(p3 * l3);
        accA += ex2f(p4 * l4);  accB += ex2f(p5 * l5);
        accA += ex2f(p6 * l6);  accB += ex2f(p7 * l7);
    }

    // ---- immediate predecessor block: eager per-column, track the wavefront ----
    for (int j = lim; j < base; ++j) {
        float l  = lg2f(fmaxf(my_sc - sc[j], 1.f));   // off-chain, before spin
        float pj = vp[j];
        while (__isnanf(pj)) { pj = vp[j]; }          // hot spin (~1 warp at a time)
        if (j & 1) accB += ex2f(pj * l);
        else       accA += ex2f(pj * l);
    }
    float acc = accA + accB;

    // ---- diagonal block: serial chain via shfl, publish for successor warps ----
    float p_mine = 0.f;
    #pragma unroll 1
    for (int k = 0; k < 32; ++k) {
        float l = lg2f(fmaxf(my_sc - sc[base + k], 1.f));  // off-chain
        if (lane == k) {
            p_mine = -fmaf(c, acc, a);
            vp[base + k] = p_mine;          // publish ASAP for successor warps
        }
        float pj = __shfl_sync(0xffffffffu, p_mine, k);
        if (lane > k) acc += ex2f(pj * l);
    }

    // ---- epilogue: sigmoid((m - tau)/s), m = log(E) ----
    if (t >= 1) {
        const float LN2 = 0.69314718055994530942f;
        const float inv_sln2 = 1.0f / (s * LN2);
        float m = lg2f(acc) * LN2;
        float e = ex2f((tau - m) * inv_sln2);
        out[(t - 1) * BATCH + b] = __fdividef(1.f, 1.f + e);
    }
}

extern "C" void kernel_launch(void* const* d_in, const int* in_sizes, int n_in,
                              void* d_out, int out_size) {
    const float* sp = (const float*)d_in[0];
    const float* w  = (const float*)d_in[1];
    float* out      = (float*)d_out;
    (void)in_sizes; (void)n_in; (void)out_size;
    actr_kernel<<<BATCH, S_LEN>>>(sp, w, out);
}

// round 9
// speedup vs baseline: 1.9742x; 1.3032x over previous
#include <cuda_runtime.h>
#include <math.h>

// ACT_R activation recurrence — wavefront column sweep (R1 structure).
// sp: [S=512, B=256, 1] f32 (sorted along S).  w: [a, c, s, tau, h].
// out: [S-1, B, 1] f32.
//
//   E_i = sum_{j<i} max(sc_i - sc_j, 1)^{p_j},  p_j = -(c*E_j + a),  E_0 = 0
//   out[i-1] = sigmoid((log(E_i) - tau)/s)
//
// One block per batch element (grid=256), one thread per row (block=512),
// NATURAL warp order (hi-wid = latest block = critical path -> arbiter
// priority). p_j published via NaN-sentinel float in smem; group-of-4
// polling with nanosleep. Diagonal 32-step chain in-warp via shfl, with the
// publish FFMA-refactored so the serial step is shfl->FMUL->ex2->FFMA.

#define S_LEN 512
#define BATCH 256

__device__ __forceinline__ float ex2f(float x) {
    float y; asm("ex2.approx.ftz.f32 %0, %1;" : "=f"(y) : "f"(x)); return y;
}
__device__ __forceinline__ float lg2f(float x) {
    float y; asm("lg2.approx.ftz.f32 %0, %1;" : "=f"(y) : "f"(x)); return y;
}
__device__ __forceinline__ float4 lds_v4_vol(const float* p) {
    float4 v; unsigned a = (unsigned)__cvta_generic_to_shared(p);
    asm volatile("ld.volatile.shared.v4.f32 {%0,%1,%2,%3}, [%4];"
                 : "=f"(v.x), "=f"(v.y), "=f"(v.z), "=f"(v.w) : "r"(a));
    return v;
}

__global__ void __launch_bounds__(S_LEN, 2)
actr_kernel(const float* __restrict__ sp, const float* __restrict__ w,
            float* __restrict__ out) {
    __shared__ __align__(16) float sc[S_LEN];   // scaled timestamps
    __shared__ __align__(16) float psm[S_LEN];  // published p_j (NaN = not ready)

    const int b    = blockIdx.x;
    const int t    = threadIdx.x;          // owned row (natural order)
    const int lane = t & 31;
    const int base = t & ~31;              // this warp's diagonal base row

    const float a = w[0], c = w[1], s = w[2], tau = w[3], h = w[4];
    const float scale = 86400.0f * h;

    const float my_sc = sp[t * BATCH + b] * scale;
    sc[t]  = my_sc;
    psm[t] = __int_as_float(0x7fc00000);   // NaN sentinel
    __syncthreads();

    volatile float* vp = psm;
    float accA = 0.f, accB = 0.f;          // dual accumulators for FADD ILP

    // ---- off-diagonal columns j = 0 .. base-1, groups of 4 ----
    for (int j = 0; j < base; j += 4) {
        // lg2s depend only on timestamps: issue BEFORE the poll to fill waits
        const float4 s4 = *reinterpret_cast<const float4*>(&sc[j]);
        float l0 = lg2f(fmaxf(my_sc - s4.x, 1.f));
        float l1 = lg2f(fmaxf(my_sc - s4.y, 1.f));
        float l2 = lg2f(fmaxf(my_sc - s4.z, 1.f));
        float l3 = lg2f(fmaxf(my_sc - s4.w, 1.f));
        // publishes are strictly in column order: once j+3 is ready, all are
        float p3 = vp[j + 3];
        while (__isnanf(p3)) { __nanosleep(40); p3 = vp[j + 3]; }
        asm volatile("" ::: "memory");     // keep group read below the poll
        float4 p4 = lds_v4_vol(&psm[j]);
        accA += ex2f(p4.x * l0);  accB += ex2f(p4.y * l1);
        accA += ex2f(p4.z * l2);  accB += ex2f(p4.w * l3);
    }
    float acc = accA + accB;

    // ---- diagonal block: serial chain via shfl ----
    // q = -(c*acc + a) over all columns accumulated so far (off-chain).
    // Lane k+1's publish value: p = q_prev + (-c) * term_k  (one FFMA on chain).
    const float negc = -c;
    float q = -fmaf(c, acc, a);            // valid p for lane 0 (cols < base)
    float p_mine = q;
    #pragma unroll 1
    for (int k = 0; k < 31; ++k) {
        float l = lg2f(fmaxf(my_sc - sc[base + k], 1.f));  // off-chain
        if (lane == k) vp[base + k] = p_mine;  // publish for successor warps
        float pj = __shfl_sync(0xffffffffu, p_mine, k);
        float term = ex2f(pj * l);
        if (lane == k + 1) p_mine = fmaf(negc, term, q);   // fast-path publish
        if (lane > k) {
            acc += term;                   // off-chain bookkeeping
            q = -fmaf(c, acc, a);          // q for the lane's later fast-path
        }
    }
    if (lane == 31) vp[base + 31] = p_mine;   // last column for successor warps

    // ---- epilogue: sigmoid((m - tau)/s), m = log(E) ----
    if (t >= 1) {
        const float LN2 = 0.69314718055994530942f;
        const float inv_sln2 = 1.0f / (s * LN2);
        float m = lg2f(acc) * LN2;
        float e = ex2f((tau - m) * inv_sln2);
        out[(t - 1) * BATCH + b] = __fdividef(1.f, 1.f + e);
    }
}

extern "C" void kernel_launch(void* const* d_in, const int* in_sizes, int n_in,
                              void* d_out, int out_size) {
    const float* sp = (const float*)d_in[0];
    const float* w  = (const float*)d_in[1];
    float* out      = (float*)d_out;
    (void)in_sizes; (void)n_in; (void)out_size;
    actr_kernel<<<BATCH, S_LEN>>>(sp, w, out);
}